// round 2
// baseline (speedup 1.0000x reference)
#include <cuda_runtime.h>
#include <cuda_bf16.h>

#define D_DIM 256
#define N_MAX 16384
#define K_MAX 8192

#define BM 64
#define BN 128
#define BK 16
#define TM 8
#define TN 8
#define NTHREADS 128   // (BN/TN)=16 cols x (BM/TM)=8 rows

// Scratch (allocation-free rule: device globals)
__device__ float g_xsq[N_MAX];
__device__ float g_esq[K_MAX];

// -------- sum-of-squares per row, warp per row --------
__global__ void sumsq_kernel(const float* __restrict__ x, float* __restrict__ out, int rows) {
    int warps_per_blk = blockDim.x >> 5;
    int row = blockIdx.x * warps_per_blk + (threadIdx.x >> 5);
    if (row >= rows) return;
    int lane = threadIdx.x & 31;
    const float* p = x + (size_t)row * D_DIM;
    float s = 0.f;
    #pragma unroll
    for (int c = lane; c < D_DIM; c += 32) { float v = p[c]; s += v * v; }
    #pragma unroll
    for (int o = 16; o; o >>= 1) s += __shfl_down_sync(0xffffffffu, s, o);
    if (lane == 0) out[row] = s;
}

// -------- fused distance-GEMM + argmin + gather --------
__global__ __launch_bounds__(NTHREADS)
void vq_argmin_kernel(const float* __restrict__ X, const float* __restrict__ E,
                      const float* __restrict__ xsq, const float* __restrict__ esq,
                      float* __restrict__ outq, float* __restrict__ outi,
                      int N, int K)
{
    __shared__ float Xs[BK][BM];
    __shared__ float Es[BK][BN];
    __shared__ float s_bd[16][BM];
    __shared__ int   s_bi[16][BM];
    __shared__ int   s_idx[BM];

    const int tid = threadIdx.x;
    const int tx = tid & 15;   // col group 0..15 -> cols tx*8..tx*8+7
    const int ty = tid >> 4;   // row group 0..7  -> rows ty*8..ty*8+7
    const int n0 = blockIdx.x * BM;

    float bestd[TM];
    int   besti[TM];
    float xq[TM];
    #pragma unroll
    for (int i = 0; i < TM; i++) {
        bestd[i] = 3.4e38f;
        besti[i] = 0x7fffffff;
        xq[i] = xsq[n0 + ty * TM + i];
    }

    for (int k0 = 0; k0 < K; k0 += BN) {
        float acc[TM][TN];
        #pragma unroll
        for (int i = 0; i < TM; i++)
            #pragma unroll
            for (int j = 0; j < TN; j++) acc[i][j] = 0.f;

        for (int d0 = 0; d0 < D_DIM; d0 += BK) {
            // X tile: 64 rows x 16 cols = 256 float4, 2 per thread
            #pragma unroll
            for (int l = 0; l < 2; l++) {
                int f  = tid + l * NTHREADS;     // 0..255
                int r  = f >> 2;                 // row 0..63
                int c4 = f & 3;                  // float4 slot within 16-wide row
                float4 v = *(const float4*)(X + (size_t)(n0 + r) * D_DIM + d0 + c4 * 4);
                Xs[c4 * 4 + 0][r] = v.x;
                Xs[c4 * 4 + 1][r] = v.y;
                Xs[c4 * 4 + 2][r] = v.z;
                Xs[c4 * 4 + 3][r] = v.w;
            }
            // E tile: 128 rows x 16 cols = 512 float4, 4 per thread
            #pragma unroll
            for (int l = 0; l < 4; l++) {
                int f  = tid + l * NTHREADS;     // 0..511
                int r  = f >> 2;                 // row 0..127
                int c4 = f & 3;
                float4 v = *(const float4*)(E + (size_t)(k0 + r) * D_DIM + d0 + c4 * 4);
                Es[c4 * 4 + 0][r] = v.x;
                Es[c4 * 4 + 1][r] = v.y;
                Es[c4 * 4 + 2][r] = v.z;
                Es[c4 * 4 + 3][r] = v.w;
            }
            __syncthreads();

            #pragma unroll
            for (int kk = 0; kk < BK; kk++) {
                float xr[TM], er[TN];
                #pragma unroll
                for (int i = 0; i < TM; i++) xr[i] = Xs[kk][ty * TM + i];
                #pragma unroll
                for (int j = 0; j < TN; j++) er[j] = Es[kk][tx * TN + j];
                #pragma unroll
                for (int i = 0; i < TM; i++)
                    #pragma unroll
                    for (int j = 0; j < TN; j++)
                        acc[i][j] = fmaf(xr[i], er[j], acc[i][j]);
            }
            __syncthreads();
        }

        // fold this 128-code tile into the running argmin
        #pragma unroll
        for (int i = 0; i < TM; i++) {
            #pragma unroll
            for (int j = 0; j < TN; j++) {
                int col = k0 + tx * TN + j;
                float d = xq[i] + esq[col] - 2.f * acc[i][j];
                if (d < bestd[i] || (d == bestd[i] && col < besti[i])) {
                    bestd[i] = d;
                    besti[i] = col;
                }
            }
        }
    }

    // cross-column-group reduction (16 candidates per row)
    #pragma unroll
    for (int i = 0; i < TM; i++) {
        s_bd[tx][ty * TM + i] = bestd[i];
        s_bi[tx][ty * TM + i] = besti[i];
    }
    __syncthreads();

    if (tid < BM) {
        float bd = s_bd[0][tid];
        int   bi = s_bi[0][tid];
        #pragma unroll
        for (int t = 1; t < 16; t++) {
            float d  = s_bd[t][tid];
            int   ii = s_bi[t][tid];
            if (d < bd || (d == bd && ii < bi)) { bd = d; bi = ii; }
        }
        s_idx[tid] = bi;
        outi[n0 + tid] = (float)bi;   // indices as float32 in concatenated output
    }
    __syncthreads();

    // gather embed[best] -> outq, 64 rows x 64 float4 = 4096 float4
    for (int f = tid; f < BM * (D_DIM / 4); f += NTHREADS) {
        int r  = f / (D_DIM / 4);
        int c4 = f % (D_DIM / 4);
        int bi = s_idx[r];
        float4 v = *(const float4*)(E + (size_t)bi * D_DIM + c4 * 4);
        *(float4*)(outq + (size_t)(n0 + r) * D_DIM + c4 * 4) = v;
    }
}

extern "C" void kernel_launch(void* const* d_in, const int* in_sizes, int n_in,
                              void* d_out, int out_size) {
    const float* X = (const float*)d_in[0];   // inputs_flatten [N, 256]
    const float* E = (const float*)d_in[1];   // embed [K, 256]
    const int N = in_sizes[0] / D_DIM;
    const int K = in_sizes[1] / D_DIM;

    float* p_xsq = nullptr;
    float* p_esq = nullptr;
    cudaGetSymbolAddress((void**)&p_xsq, g_xsq);
    cudaGetSymbolAddress((void**)&p_esq, g_esq);

    float* outq = (float*)d_out;                   // [N, 256]
    float* outi = (float*)d_out + (size_t)N * D_DIM; // [N] indices (as float)

    // sum of squares: warp per row, 8 warps per block
    {
        int wpb = 8, thr = 32 * wpb;
        sumsq_kernel<<<(N + wpb - 1) / wpb, thr>>>(X, p_xsq, N);
        sumsq_kernel<<<(K + wpb - 1) / wpb, thr>>>(E, p_esq, K);
    }

    vq_argmin_kernel<<<N / BM, NTHREADS>>>(X, E, p_xsq, p_esq, outq, outi, N, K);
}

// round 4
// speedup vs baseline: 2.2310x; 2.2310x over previous
#include <cuda_runtime.h>
#include <cstdint>

#define DD 256
#define NTOK 16384
#define KCB 8192
#define BM 128
#define BN 128
#define BK 32
#define NNT (KCB/BN)     // 64 col-tiles
#define NDC (DD/BK)      // 8 d-chunks
#define NIT (NNT*NDC)    // 512
#define LDT 36           // padded smem row (floats)
#define OPB (BM*LDT*4)   // 18432 B per operand tile
#define STGB (4*OPB)     // 73728 B per stage
#define SBD  (2*STGB)
#define SBI  (SBD + 128*16*4)
#define SIDX (SBI + 128*16*4)
#define SMEMSZ (SIDX + 512)

__device__ float g_xhi[NTOK*DD];
__device__ float g_xlo[NTOK*DD];
__device__ float g_ehi[KCB*DD];
__device__ float g_elo[KCB*DD];
__device__ float g_esq[KCB];

#define CP16(d,s)   asm volatile("cp.async.cg.shared.global [%0], [%1], 16;"::"r"(d),"l"(s):"memory")
#define CP_COMMIT() asm volatile("cp.async.commit_group;":::"memory")
#define CP_WAIT(n)  asm volatile("cp.async.wait_group %0;"::"n"(n):"memory")

__device__ __forceinline__ uint32_t s2u(const void* p){
    uint32_t a; asm("{ .reg .u64 t; cvta.to.shared.u64 t, %1; cvt.u32.u64 %0, t; }":"=r"(a):"l"(p)); return a;
}
__device__ __forceinline__ void mma8(float* d, const uint32_t* a, const uint32_t* b){
    asm("mma.sync.aligned.m16n8k8.row.col.f32.tf32.tf32.f32 "
        "{%0,%1,%2,%3}, {%4,%5,%6,%7}, {%8,%9}, {%0,%1,%2,%3};"
        : "+f"(d[0]),"+f"(d[1]),"+f"(d[2]),"+f"(d[3])
        : "r"(a[0]),"r"(a[1]),"r"(a[2]),"r"(a[3]),"r"(b[0]),"r"(b[1]));
}
__device__ __forceinline__ float tf32r(float x){
    uint32_t b; asm("cvt.rna.tf32.f32 %0, %1;":"=r"(b):"f"(x)); return __uint_as_float(b);
}

// ---- prep kernels ----
__global__ void split_kernel(const float4* __restrict__ s, float4* __restrict__ h,
                             float4* __restrict__ l, int n4){
    int i = blockIdx.x*blockDim.x + threadIdx.x; if(i>=n4) return;
    float4 v=s[i], a, b;
    a.x=tf32r(v.x); b.x=tf32r(v.x-a.x); a.y=tf32r(v.y); b.y=tf32r(v.y-a.y);
    a.z=tf32r(v.z); b.z=tf32r(v.z-a.z); a.w=tf32r(v.w); b.w=tf32r(v.w-a.w);
    h[i]=a; l[i]=b;
}
__global__ void sumsq_kernel(const float* __restrict__ x, float* __restrict__ o, int rows){
    int row = blockIdx.x*(blockDim.x>>5) + (threadIdx.x>>5); if(row>=rows) return;
    int lane = threadIdx.x&31; const float* p = x + (size_t)row*DD; float s=0.f;
    #pragma unroll
    for(int c=lane;c<DD;c+=32){ float v=p[c]; s+=v*v; }
    #pragma unroll
    for(int ofs=16;ofs;ofs>>=1) s+=__shfl_down_sync(0xffffffffu,s,ofs);
    if(!lane) o[row]=s;
}

// ---- async stage fill: 4096 x 16B, 16 per thread ----
__device__ __forceinline__ void issue_stage(uint32_t sbt, int it, int m0, int tid,
    const float* __restrict__ xhi, const float* __restrict__ xlo,
    const float* __restrict__ ehi, const float* __restrict__ elo){
    const int nt = it>>3, dc = it&7;
    const uint32_t tb = sbt + (uint32_t)(it&1)*STGB;
    #pragma unroll
    for(int i=0;i<16;i++){
        int idx = tid + i*256;
        int op = idx>>10, rem = idx&1023, row = rem>>3, c4 = rem&7;
        uint32_t dst = tb + op*OPB + row*(LDT*4) + c4*16;
        const float* src;
        if(op==0)      src = xhi + (size_t)(m0+row)*DD      + dc*32 + c4*4;
        else if(op==1) src = xlo + (size_t)(m0+row)*DD      + dc*32 + c4*4;
        else if(op==2) src = ehi + (size_t)(nt*BN+row)*DD   + dc*32 + c4*4;
        else           src = elo + (size_t)(nt*BN+row)*DD   + dc*32 + c4*4;
        CP16(dst, src);
    }
    CP_COMMIT();
}

__global__ void __launch_bounds__(256,1) vq_main(
    const float* __restrict__ xhi, const float* __restrict__ xlo,
    const float* __restrict__ ehi, const float* __restrict__ elo,
    const float* __restrict__ E,   const float* __restrict__ esq,
    float* __restrict__ outq, float* __restrict__ outi)
{
    extern __shared__ char smem[];
    const uint32_t sb = s2u(smem);
    const int tid = threadIdx.x, wid = tid>>5, lane = tid&31;
    const int r = lane>>2, c = lane&3;
    const int wm = wid&1, wn = wid>>1;
    const int m0 = blockIdx.x*BM;

    float bestd[8]; int besti[8];
    #pragma unroll
    for(int i=0;i<8;i++){ bestd[i]=3.4e38f; besti[i]=0; }

    issue_stage(sb, 0, m0, tid, xhi,xlo,ehi,elo);

    for(int nt=0; nt<NNT; nt++){
        float acc[4][4][4];
        #pragma unroll
        for(int m=0;m<4;m++)
            #pragma unroll
            for(int n=0;n<4;n++)
                #pragma unroll
                for(int q=0;q<4;q++) acc[m][n][q]=0.f;

        for(int dc=0; dc<NDC; dc++){
            const int it = nt*NDC + dc;
            if(it+1 < NIT){ issue_stage(sb, it+1, m0, tid, xhi,xlo,ehi,elo); CP_WAIT(1); }
            else          { CP_WAIT(0); }
            __syncthreads();
            const char* stp = smem + (size_t)(it&1)*STGB;

            #pragma unroll
            for(int ks=0; ks<4; ks++){
                uint32_t ah[4][4], al[4][4], bh[4][2], bl[4][2];
                #pragma unroll
                for(int m=0;m<4;m++){
                    int off = ((wm*64 + m*16 + r)*LDT + ks*8 + c)*4;
                    ah[m][0]=*(const uint32_t*)(stp+off);
                    ah[m][1]=*(const uint32_t*)(stp+off+8*LDT*4);
                    ah[m][2]=*(const uint32_t*)(stp+off+16);
                    ah[m][3]=*(const uint32_t*)(stp+off+8*LDT*4+16);
                    al[m][0]=*(const uint32_t*)(stp+off+OPB);
                    al[m][1]=*(const uint32_t*)(stp+off+OPB+8*LDT*4);
                    al[m][2]=*(const uint32_t*)(stp+off+OPB+16);
                    al[m][3]=*(const uint32_t*)(stp+off+OPB+8*LDT*4+16);
                }
                #pragma unroll
                for(int n=0;n<4;n++){
                    int off = 2*OPB + ((wn*32 + n*8 + r)*LDT + ks*8 + c)*4;
                    bh[n][0]=*(const uint32_t*)(stp+off);
                    bh[n][1]=*(const uint32_t*)(stp+off+16);
                    bl[n][0]=*(const uint32_t*)(stp+off+OPB);
                    bl[n][1]=*(const uint32_t*)(stp+off+OPB+16);
                }
                #pragma unroll
                for(int m=0;m<4;m++)
                    #pragma unroll
                    for(int n=0;n<4;n++){
                        mma8(acc[m][n], ah[m], bh[n]);
                        mma8(acc[m][n], ah[m], bl[n]);
                        mma8(acc[m][n], al[m], bh[n]);
                    }
            }
            __syncthreads();
        }

        // fold distances of this 128-col tile into running argmin
        #pragma unroll
        for(int m=0;m<4;m++)
            #pragma unroll
            for(int n=0;n<4;n++){
                int colb = nt*BN + wn*32 + n*8 + 2*c;
                float e0 = __ldg(esq+colb), e1 = __ldg(esq+colb+1);
                int rl = m*2, rh = m*2+1;
                float d;
                d = e0 - 2.f*acc[m][n][0]; if(d<bestd[rl]){bestd[rl]=d;besti[rl]=colb;}
                d = e1 - 2.f*acc[m][n][1]; if(d<bestd[rl]){bestd[rl]=d;besti[rl]=colb+1;}
                d = e0 - 2.f*acc[m][n][2]; if(d<bestd[rh]){bestd[rh]=d;besti[rh]=colb;}
                d = e1 - 2.f*acc[m][n][3]; if(d<bestd[rh]){bestd[rh]=d;besti[rh]=colb+1;}
            }
    }

    // cross-thread reduce: 16 candidates per row
    float* s_bd = (float*)(smem + SBD);
    int*   s_bi = (int*)(smem + SBI);
    int*   s_idx= (int*)(smem + SIDX);
    __syncthreads();
    #pragma unroll
    for(int i=0;i<8;i++){
        int row  = wm*64 + (i>>1)*16 + r + (i&1)*8;
        int slot = wn*4 + c;
        s_bd[row*16+slot] = bestd[i];
        s_bi[row*16+slot] = besti[i];
    }
    __syncthreads();
    if(tid < 128){
        float bd = s_bd[tid*16]; int bi = s_bi[tid*16];
        #pragma unroll
        for(int t=1;t<16;t++){
            float d = s_bd[tid*16+t]; int ii = s_bi[tid*16+t];
            if(d<bd || (d==bd && ii<bi)){ bd=d; bi=ii; }
        }
        s_idx[tid] = bi;
        outi[m0+tid] = (float)bi;
    }
    __syncthreads();
    // gather exact fp32 codebook rows
    for(int f=tid; f<BM*(DD/4); f+=256){
        int rr = f>>6, c4 = f&63;
        float4 v = *(const float4*)(E + (size_t)s_idx[rr]*DD + c4*4);
        *(float4*)(outq + (size_t)(m0+rr)*DD + c4*4) = v;
    }
}

extern "C" void kernel_launch(void* const* d_in, const int* in_sizes, int n_in,
                              void* d_out, int out_size) {
    const float* X = (const float*)d_in[0];
    const float* E = (const float*)d_in[1];

    float *xhi,*xlo,*ehi,*elo,*esq;
    cudaGetSymbolAddress((void**)&xhi, g_xhi);
    cudaGetSymbolAddress((void**)&xlo, g_xlo);
    cudaGetSymbolAddress((void**)&ehi, g_ehi);
    cudaGetSymbolAddress((void**)&elo, g_elo);
    cudaGetSymbolAddress((void**)&esq, g_esq);

    split_kernel<<<NTOK*DD/4/256, 256>>>((const float4*)X, (float4*)xhi, (float4*)xlo, NTOK*DD/4);
    split_kernel<<<KCB*DD/4/256, 256>>>((const float4*)E, (float4*)ehi, (float4*)elo, KCB*DD/4);
    sumsq_kernel<<<KCB/8, 256>>>(E, esq, KCB);

    float* outq = (float*)d_out;
    float* outi = (float*)d_out + (size_t)NTOK*DD;

    cudaFuncSetAttribute(vq_main, cudaFuncAttributeMaxDynamicSharedMemorySize, SMEMSZ);
    vq_main<<<NTOK/BM, 256, SMEMSZ>>>(xhi,xlo,ehi,elo, E, esq, outq, outi);
}